// round 1
// baseline (speedup 1.0000x reference)
#include <cuda_runtime.h>

#define B_ 8
#define N_ 65536
#define H_ 56
#define W_ 56
#define C_ 128
#define TOTPTS (B_*N_)
#define FEATTOT (B_*C_*H_*W_)
#define BD 384

typedef unsigned long long u64;

// NHWC-transposed feature scratch (12.8 MB) — __device__ global (no allocs allowed)
__device__ float g_feat_nhwc[FEATTOT];

__global__ void __launch_bounds__(256) transpose_kernel(const float* __restrict__ f) {
    int idx = blockIdx.x * 256 + threadIdx.x;
    if (idx >= FEATTOT) return;
    int c = idx & (C_ - 1);
    int rest = idx >> 7;
    int w = rest % W_;
    int r2 = rest / W_;
    int h = r2 % H_;
    int b = r2 / H_;
    g_feat_nhwc[idx] = f[((b * C_ + c) * H_ + h) * W_ + w];
}

__device__ __forceinline__ u64 pk2(float lo, float hi) {
    u64 r; asm("mov.b64 %0, {%1, %2};" : "=l"(r) : "f"(lo), "f"(hi)); return r;
}
__device__ __forceinline__ void upk2(u64 v, float& lo, float& hi) {
    asm("mov.b64 {%0, %1}, %2;" : "=f"(lo), "=f"(hi) : "l"(v));
}
// Packed fp32x2 FMA (sm_100+): acc.lo += a.lo*b.lo ; acc.hi += a.hi*b.hi
__device__ __forceinline__ void fma2(u64& acc, u64 a, u64 b) {
    asm("fma.rn.f32x2 %0, %1, %2, %0;" : "+l"(acc) : "l"(a), "l"(b));
}

// shared-memory layout (float offsets)
#define OFF_W1 0
#define OFF_W2 16384
#define OFF_W3 20480
#define OFF_W4 24576
#define OFF_B1 24640
#define OFF_B2 24704
#define OFF_B3 24768
#define OFF_BG 24832
#define OFF_B4 25024
#define OFF_H  25032
#define SMEM_FLOATS (OFF_H + 64*BD)
#define SMEM_BYTES (SMEM_FLOATS * 4)

__global__ void __launch_bounds__(BD) decoder_kernel(
    const float* __restrict__ points, const float* __restrict__ kmat,
    const float* __restrict__ rt, const float* __restrict__ Bg,
    const float* __restrict__ W1, const float* __restrict__ b1,
    const float* __restrict__ W2, const float* __restrict__ b2,
    const float* __restrict__ W3, const float* __restrict__ b3,
    const float* __restrict__ W4, const float* __restrict__ b4,
    float* __restrict__ out)
{
    extern __shared__ float s[];

    // cooperative stage of all weights into shared
    for (int t = threadIdx.x; t < 16384; t += BD) s[OFF_W1 + t] = W1[t];
    for (int t = threadIdx.x; t < 4096; t += BD) s[OFF_W2 + t] = W2[t];
    for (int t = threadIdx.x; t < 4096; t += BD) s[OFF_W3 + t] = W3[t];
    for (int t = threadIdx.x; t < 64; t += BD) {
        s[OFF_W4 + t] = W4[t]; s[OFF_B1 + t] = b1[t];
        s[OFF_B2 + t] = b2[t]; s[OFF_B3 + t] = b3[t];
    }
    for (int t = threadIdx.x; t < 192; t += BD) s[OFF_BG + t] = Bg[t];
    if (threadIdx.x == 0) s[OFF_B4] = b4[0];
    __syncthreads();

    int tid = threadIdx.x;
    int pidx = blockIdx.x * BD + tid;
    if (pidx >= TOTPTS) return;
    int b = pidx >> 16;

    float px = points[pidx*3 + 0];
    float py = points[pidx*3 + 1];
    float pz = points[pidx*3 + 2];

    // ---- camera projection (two-step, like reference) ----
    const float* rtb = rt + b*12;
    const float* kb  = kmat + b*9;
    float c0 = rtb[0]*px + rtb[1]*py + rtb[2]*pz + rtb[3];
    float c1 = rtb[4]*px + rtb[5]*py + rtb[6]*pz + rtb[7];
    float c2 = rtb[8]*px + rtb[9]*py + rtb[10]*pz + rtb[11];
    float i0 = kb[0]*c0 + kb[1]*c1 + kb[2]*c2;
    float i1 = kb[3]*c0 + kb[4]*c1 + kb[5]*c2;
    float i2 = kb[6]*c0 + kb[7]*c1 + kb[8]*c2;
    float zb = i2 + 1e-8f;
    float u = i0 / zb, v = i1 / zb;
    float validf = (i2 > 0.0f) ? 1.0f : 0.0f;
    float un = (2.0f*u + 1.0f) / 56.0f - 1.0f;
    float vn = (2.0f*v + 1.0f) / 56.0f - 1.0f;
    float xp = ((un + 1.0f) * 56.0f - 1.0f) * 0.5f;
    float yp = ((vn + 1.0f) * 56.0f - 1.0f) * 0.5f;
    float x0f = floorf(xp), y0f = floorf(yp);
    float fx = xp - x0f, fy = yp - y0f;
    float gx0 = 1.0f - fx, gy0 = 1.0f - fy;
    int ix0 = (int)x0f, iy0 = (int)y0f;
    int ix1 = ix0 + 1, iy1 = iy0 + 1;
    float m00 = (ix0 >= 0 && ix0 < W_ && iy0 >= 0 && iy0 < H_) ? validf : 0.0f;
    float m10 = (ix1 >= 0 && ix1 < W_ && iy0 >= 0 && iy0 < H_) ? validf : 0.0f;
    float m01 = (ix0 >= 0 && ix0 < W_ && iy1 >= 0 && iy1 < H_) ? validf : 0.0f;
    float m11 = (ix1 >= 0 && ix1 < W_ && iy1 >= 0 && iy1 < H_) ? validf : 0.0f;
    float w00 = gx0*gy0*m00, w10 = fx*gy0*m10, w01 = gx0*fy*m01, w11 = fx*fy*m11;
    int cx0 = min(max(ix0, 0), W_-1), cx1 = min(max(ix1, 0), W_-1);
    int cy0 = min(max(iy0, 0), H_-1), cy1 = min(max(iy1, 0), H_-1);
    const float* p00 = g_feat_nhwc + (((b*H_ + cy0)*W_ + cx0) << 7);
    const float* p10 = g_feat_nhwc + (((b*H_ + cy0)*W_ + cx1) << 7);
    const float* p01 = g_feat_nhwc + (((b*H_ + cy1)*W_ + cx0) << 7);
    const float* p11 = g_feat_nhwc + (((b*H_ + cy1)*W_ + cx1) << 7);

    // ---- layer 1 accumulators (32 packed f32x2 = 64 outputs) ----
    const u64* sW1p = (const u64*)(s + OFF_W1);   // [256 rows][32 pairs]
    u64 acc[32];
    {
        const u64* bp = (const u64*)(s + OFF_B1);
        #pragma unroll
        for (int jp = 0; jp < 32; jp++) acc[jp] = bp[jp];
    }

    // ---- image features: 32 groups of 4 channels, prefetched double-buffer ----
    float4 n00 = *(const float4*)(p00);
    float4 n10 = *(const float4*)(p10);
    float4 n01 = *(const float4*)(p01);
    float4 n11 = *(const float4*)(p11);
    #pragma unroll 1
    for (int g = 0; g < 32; g++) {
        float4 v00 = n00, v10 = n10, v01 = n01, v11 = n11;
        if (g < 31) {
            n00 = *(const float4*)(p00 + (g+1)*4);
            n10 = *(const float4*)(p10 + (g+1)*4);
            n01 = *(const float4*)(p01 + (g+1)*4);
            n11 = *(const float4*)(p11 + (g+1)*4);
        }
        float f0 = w00*v00.x + w10*v10.x + w01*v01.x + w11*v11.x;
        float f1 = w00*v00.y + w10*v10.y + w01*v01.y + w11*v11.y;
        float f2 = w00*v00.z + w10*v10.z + w01*v01.z + w11*v11.z;
        float f3 = w00*v00.w + w10*v10.w + w01*v01.w + w11*v11.w;
        u64 d0 = pk2(f0, f0), d1 = pk2(f1, f1), d2 = pk2(f2, f2), d3 = pk2(f3, f3);
        const u64* wr = sW1p + g*128;
        #pragma unroll
        for (int jp = 0; jp < 32; jp++) fma2(acc[jp], d0, wr[jp]);
        #pragma unroll
        for (int jp = 0; jp < 32; jp++) fma2(acc[jp], d1, wr[32 + jp]);
        #pragma unroll
        for (int jp = 0; jp < 32; jp++) fma2(acc[jp], d2, wr[64 + jp]);
        #pragma unroll
        for (int jp = 0; jp < 32; jp++) fma2(acc[jp], d3, wr[96 + jp]);
    }

    // ---- Fourier features: sin rows 128..191, cos rows 192..255 ----
    const float* sBg = s + OFF_BG;
    #pragma unroll 1
    for (int m = 0; m < 64; m++) {
        float dot = px*sBg[m*3] + py*sBg[m*3+1] + pz*sBg[m*3+2];
        float pm = 6.28318530717958647692f * dot;
        float sv, cv;
        sincosf(pm, &sv, &cv);
        u64 ds = pk2(sv, sv), dc = pk2(cv, cv);
        const u64* wrs = sW1p + (128 + m)*32;
        const u64* wrc = sW1p + (192 + m)*32;
        #pragma unroll
        for (int jp = 0; jp < 32; jp++) fma2(acc[jp], ds, wrs[jp]);
        #pragma unroll
        for (int jp = 0; jp < 32; jp++) fma2(acc[jp], dc, wrc[jp]);
    }

    // ---- relu -> per-thread shared scratch (avoids dynamic register indexing) ----
    float* hs = s + OFF_H;
    #pragma unroll
    for (int jp = 0; jp < 32; jp++) {
        float lo, hi; upk2(acc[jp], lo, hi);
        hs[(2*jp)*BD + tid]   = fmaxf(lo, 0.0f);
        hs[(2*jp+1)*BD + tid] = fmaxf(hi, 0.0f);
    }

    // ---- layer 2 ----
    u64 acc2[32];
    {
        const u64* bp = (const u64*)(s + OFF_B2);
        #pragma unroll
        for (int jp = 0; jp < 32; jp++) acc2[jp] = bp[jp];
    }
    {
        const u64* sW2p = (const u64*)(s + OFF_W2);
        #pragma unroll 1
        for (int i = 0; i < 64; i++) {
            float hv = hs[i*BD + tid];
            u64 d = pk2(hv, hv);
            const u64* wr = sW2p + i*32;
            #pragma unroll
            for (int jp = 0; jp < 32; jp++) fma2(acc2[jp], d, wr[jp]);
        }
    }
    #pragma unroll
    for (int jp = 0; jp < 32; jp++) {
        float lo, hi; upk2(acc2[jp], lo, hi);
        hs[(2*jp)*BD + tid]   = fmaxf(lo, 0.0f);
        hs[(2*jp+1)*BD + tid] = fmaxf(hi, 0.0f);
    }

    // ---- layer 3 ----
    u64 acc3[32];
    {
        const u64* bp = (const u64*)(s + OFF_B3);
        #pragma unroll
        for (int jp = 0; jp < 32; jp++) acc3[jp] = bp[jp];
    }
    {
        const u64* sW3p = (const u64*)(s + OFF_W3);
        #pragma unroll 1
        for (int i = 0; i < 64; i++) {
            float hv = hs[i*BD + tid];
            u64 d = pk2(hv, hv);
            const u64* wr = sW3p + i*32;
            #pragma unroll
            for (int jp = 0; jp < 32; jp++) fma2(acc3[jp], d, wr[jp]);
        }
    }

    // ---- layer 4: relu(h3) . W4 + b4 ----
    const float* sW4 = s + OFF_W4;
    float o = s[OFF_B4];
    #pragma unroll
    for (int jp = 0; jp < 32; jp++) {
        float lo, hi; upk2(acc3[jp], lo, hi);
        o = fmaf(fmaxf(lo, 0.0f), sW4[2*jp], o);
        o = fmaf(fmaxf(hi, 0.0f), sW4[2*jp+1], o);
    }
    out[pidx] = o;
}

extern "C" void kernel_launch(void* const* d_in, const int* in_sizes, int n_in,
                              void* d_out, int out_size) {
    const float* features = (const float*)d_in[0];
    const float* points   = (const float*)d_in[1];
    const float* kmat     = (const float*)d_in[2];
    const float* rt       = (const float*)d_in[3];
    const float* Bg       = (const float*)d_in[4];
    const float* W1       = (const float*)d_in[5];
    const float* b1       = (const float*)d_in[6];
    const float* W2       = (const float*)d_in[7];
    const float* b2       = (const float*)d_in[8];
    const float* W3       = (const float*)d_in[9];
    const float* b3       = (const float*)d_in[10];
    const float* W4       = (const float*)d_in[11];
    const float* b4       = (const float*)d_in[12];
    float* out = (float*)d_out;

    transpose_kernel<<<FEATTOT/256, 256>>>(features);

    cudaFuncSetAttribute(decoder_kernel,
                         cudaFuncAttributeMaxDynamicSharedMemorySize, SMEM_BYTES);
    decoder_kernel<<<(TOTPTS + BD - 1)/BD, BD, SMEM_BYTES>>>(
        points, kmat, rt, Bg, W1, b1, W2, b2, W3, b3, W4, b4, out);
}

// round 5
// speedup vs baseline: 1.1688x; 1.1688x over previous
#include <cuda_runtime.h>
#include <math.h>

#define B_ 8
#define H_ 56
#define W_ 56
#define C_ 128
#define TOTPTS (B_*65536)
#define FEATTOT (B_*C_*H_*W_)
#define BD 256
#define PPB 512

typedef unsigned long long u64;

// NHWC-transposed feature scratch (12.8 MB), 128B-aligned so each 512B pixel row
// starts on a cache-line boundary.
__device__ __align__(128) float g_feat_nhwc[FEATTOT];

__global__ void __launch_bounds__(256) transpose_kernel(const float* __restrict__ f) {
    int idx = blockIdx.x * 256 + threadIdx.x;
    if (idx >= FEATTOT) return;
    int c = idx & (C_ - 1);
    int rest = idx >> 7;
    int w = rest % W_;
    int r2 = rest / W_;
    int h = r2 % H_;
    int b = r2 / H_;
    g_feat_nhwc[idx] = f[((b * C_ + c) * H_ + h) * W_ + w];
}

__device__ __forceinline__ u64 pk2(float lo, float hi) {
    u64 r; asm("mov.b64 %0, {%1, %2};" : "=l"(r) : "f"(lo), "f"(hi)); return r;
}
__device__ __forceinline__ void upk2(u64 v, float& lo, float& hi) {
    asm("mov.b64 {%0, %1}, %2;" : "=f"(lo), "=f"(hi) : "l"(v));
}
__device__ __forceinline__ void fma2(u64& acc, u64 a, u64 b) {
    asm("fma.rn.f32x2 %0, %1, %2, %0;" : "+l"(acc) : "l"(a), "l"(b));
}
__device__ __forceinline__ u64 relu2(u64 v) {
    float lo, hi; upk2(v, lo, hi);
    return pk2(fmaxf(lo, 0.0f), fmaxf(hi, 0.0f));
}

// shared layout (float offsets)
#define OFF_W1   0        // 16384  W1 [256][64]
#define OFF_W2   16384    // 4096
#define OFF_W3   20480    // 4096
#define OFF_W4   24576    // 64
#define OFF_B1   24640    // 64
#define OFF_B2   24704    // 64
#define OFF_B3   24768    // 64
#define OFF_BG4  24832    // 256 (64 x float4, padded Bg rows)
#define OFF_B4   25088    // 4 (1 used)
#define OFF_TBLW 25092    // 2048 (512 pts x 4 bilinear weights)
#define OFF_TBLB 27140    // 2048 (512 pts x 4 corner bases, int)
#define OFF_STG  29188    // 16896 (512 rows x 33 floats; reused as 64x256 tail scratch)
#define SMEM_FLOATS (OFF_STG + 16896)
#define SMEM_BYTES  (SMEM_FLOATS * 4)

__device__ __forceinline__ void project_point(
    const float* __restrict__ points, const float* __restrict__ kmat,
    const float* __restrict__ rt, int pidx,
    float* tw, int* tb, float& opx, float& opy, float& opz)
{
    int b = pidx >> 16;
    float px = points[pidx*3 + 0];
    float py = points[pidx*3 + 1];
    float pz = points[pidx*3 + 2];
    opx = px; opy = py; opz = pz;
    const float* rtb = rt + b*12;
    const float* kb  = kmat + b*9;
    float c0 = rtb[0]*px + rtb[1]*py + rtb[2]*pz + rtb[3];
    float c1 = rtb[4]*px + rtb[5]*py + rtb[6]*pz + rtb[7];
    float c2 = rtb[8]*px + rtb[9]*py + rtb[10]*pz + rtb[11];
    float i0 = kb[0]*c0 + kb[1]*c1 + kb[2]*c2;
    float i1 = kb[3]*c0 + kb[4]*c1 + kb[5]*c2;
    float i2 = kb[6]*c0 + kb[7]*c1 + kb[8]*c2;
    float zb = i2 + 1e-8f;
    float u = i0 / zb, v = i1 / zb;
    float validf = (i2 > 0.0f) ? 1.0f : 0.0f;
    float un = (2.0f*u + 1.0f) / 56.0f - 1.0f;
    float vn = (2.0f*v + 1.0f) / 56.0f - 1.0f;
    float xp = ((un + 1.0f) * 56.0f - 1.0f) * 0.5f;
    float yp = ((vn + 1.0f) * 56.0f - 1.0f) * 0.5f;
    float x0f = floorf(xp), y0f = floorf(yp);
    float fx = xp - x0f, fy = yp - y0f;
    float gx0 = 1.0f - fx, gy0 = 1.0f - fy;
    int ix0 = (int)x0f, iy0 = (int)y0f;
    int ix1 = ix0 + 1, iy1 = iy0 + 1;
    float m00 = (ix0 >= 0 && ix0 < W_ && iy0 >= 0 && iy0 < H_) ? validf : 0.0f;
    float m10 = (ix1 >= 0 && ix1 < W_ && iy0 >= 0 && iy0 < H_) ? validf : 0.0f;
    float m01 = (ix0 >= 0 && ix0 < W_ && iy1 >= 0 && iy1 < H_) ? validf : 0.0f;
    float m11 = (ix1 >= 0 && ix1 < W_ && iy1 >= 0 && iy1 < H_) ? validf : 0.0f;
    tw[0] = gx0*gy0*m00; tw[1] = fx*gy0*m10; tw[2] = gx0*fy*m01; tw[3] = fx*fy*m11;
    int cx0 = min(max(ix0, 0), W_-1), cx1 = min(max(ix1, 0), W_-1);
    int cy0 = min(max(iy0, 0), H_-1), cy1 = min(max(iy1, 0), H_-1);
    tb[0] = ((b*H_ + cy0)*W_ + cx0) << 7;
    tb[1] = ((b*H_ + cy0)*W_ + cx1) << 7;
    tb[2] = ((b*H_ + cy1)*W_ + cx0) << 7;
    tb[3] = ((b*H_ + cy1)*W_ + cx1) << 7;
}

// layers 2..4 for one point; h1 in hs column tid (hs[i*BD + tid])
__device__ __forceinline__ float mlp_tail(const float* __restrict__ s,
                                          float* __restrict__ hs, int tid) {
    u64 acc[32];
    {
        const ulonglong2* bp = (const ulonglong2*)(s + OFF_B2);
        #pragma unroll
        for (int t = 0; t < 16; t++) { ulonglong2 v = bp[t]; acc[2*t] = v.x; acc[2*t+1] = v.y; }
    }
    #pragma unroll 1
    for (int i = 0; i < 64; i++) {
        float hv = hs[i*BD + tid];
        u64 d = pk2(hv, hv);
        const ulonglong2* wr = (const ulonglong2*)(s + OFF_W2 + i*64);
        #pragma unroll
        for (int t = 0; t < 16; t++) {
            ulonglong2 w = wr[t];
            fma2(acc[2*t], d, w.x); fma2(acc[2*t+1], d, w.y);
        }
    }
    #pragma unroll
    for (int t = 0; t < 32; t++) {
        float lo, hi; upk2(relu2(acc[t]), lo, hi);
        hs[(2*t)*BD + tid] = lo; hs[(2*t+1)*BD + tid] = hi;
    }
    u64 acc3[32];
    {
        const ulonglong2* bp = (const ulonglong2*)(s + OFF_B3);
        #pragma unroll
        for (int t = 0; t < 16; t++) { ulonglong2 v = bp[t]; acc3[2*t] = v.x; acc3[2*t+1] = v.y; }
    }
    #pragma unroll 1
    for (int i = 0; i < 64; i++) {
        float hv = hs[i*BD + tid];
        u64 d = pk2(hv, hv);
        const ulonglong2* wr = (const ulonglong2*)(s + OFF_W3 + i*64);
        #pragma unroll
        for (int t = 0; t < 16; t++) {
            ulonglong2 w = wr[t];
            fma2(acc3[2*t], d, w.x); fma2(acc3[2*t+1], d, w.y);
        }
    }
    float o = s[OFF_B4];
    #pragma unroll
    for (int t = 0; t < 32; t++) {
        float lo, hi; upk2(acc3[t], lo, hi);
        o = fmaf(fmaxf(lo, 0.0f), s[OFF_W4 + 2*t],   o);
        o = fmaf(fmaxf(hi, 0.0f), s[OFF_W4 + 2*t+1], o);
    }
    return o;
}

__global__ void __launch_bounds__(BD) decoder_kernel(
    const float* __restrict__ points, const float* __restrict__ kmat,
    const float* __restrict__ rt, const float* __restrict__ Bg,
    const float* __restrict__ W1, const float* __restrict__ b1,
    const float* __restrict__ W2, const float* __restrict__ b2,
    const float* __restrict__ W3, const float* __restrict__ b3,
    const float* __restrict__ W4, const float* __restrict__ b4,
    float* __restrict__ out)
{
    extern __shared__ __align__(16) float s[];
    int tid = threadIdx.x;

    // ---- stage weights (all threads reach the barrier; no divergence hazards) ----
    for (int t = tid; t < 16384; t += BD) s[OFF_W1 + t] = W1[t];
    for (int t = tid; t < 4096; t += BD) { s[OFF_W2 + t] = W2[t]; s[OFF_W3 + t] = W3[t]; }
    if (tid < 64) {
        s[OFF_W4 + tid] = W4[tid]; s[OFF_B1 + tid] = b1[tid];
        s[OFF_B2 + tid] = b2[tid]; s[OFF_B3 + tid] = b3[tid];
        s[OFF_BG4 + tid*4 + 0] = Bg[tid*3 + 0];
        s[OFF_BG4 + tid*4 + 1] = Bg[tid*3 + 1];
        s[OFF_BG4 + tid*4 + 2] = Bg[tid*3 + 2];
        s[OFF_BG4 + tid*4 + 3] = 0.0f;
    }
    if (tid == 0) s[OFF_B4] = b4[0];

    int base = blockIdx.x * PPB;
    int pA = base + tid, pB = pA + BD;
    float pxA, pyA, pzA, pxB, pyB, pzB;
    project_point(points, kmat, rt, pA, s + OFF_TBLW + tid*4,
                  (int*)s + OFF_TBLB + tid*4, pxA, pyA, pzA);
    project_point(points, kmat, rt, pB, s + OFF_TBLW + (BD + tid)*4,
                  (int*)s + OFF_TBLB + (BD + tid)*4, pxB, pyB, pzB);
    __syncthreads();

    // ---- layer-1 accumulators for both points (32 pairs each) ----
    u64 accA[32], accB[32];
    {
        const ulonglong2* bp = (const ulonglong2*)(s + OFF_B1);
        #pragma unroll
        for (int t = 0; t < 16; t++) {
            ulonglong2 v = bp[t];
            accA[2*t] = v.x; accA[2*t+1] = v.y;
            accB[2*t] = v.x; accB[2*t+1] = v.y;
        }
    }

    const float* tw = s + OFF_TBLW;
    const int*   tb = (const int*)s + OFF_TBLB;
    float* stg = s + OFF_STG;

    // ---- image features: 4 quarters of 32 channels ----
    #pragma unroll 1
    for (int q = 0; q < 4; q++) {
        // gather quarter q for all 512 block points, block-coalesced:
        // task -> (point p = task>>3, chunk c = task&7); 8 consecutive lanes
        // share p, so each corner LDG.128 instruction touches only 4 lines.
        #pragma unroll 4
        for (int i = 0; i < 16; i++) {
            int task = i*BD + tid;
            int p = task >> 3, c = task & 7;
            float4 wv = *(const float4*)(tw + p*4);
            int4   bv = *(const int4*)(tb + p*4);
            int off = q*32 + c*4;
            float4 v0 = *(const float4*)(g_feat_nhwc + bv.x + off);
            float4 v1 = *(const float4*)(g_feat_nhwc + bv.y + off);
            float4 v2 = *(const float4*)(g_feat_nhwc + bv.z + off);
            float4 v3 = *(const float4*)(g_feat_nhwc + bv.w + off);
            float ax = wv.x*v0.x + wv.y*v1.x + wv.z*v2.x + wv.w*v3.x;
            float ay = wv.x*v0.y + wv.y*v1.y + wv.z*v2.y + wv.w*v3.y;
            float az = wv.x*v0.z + wv.y*v1.z + wv.z*v2.z + wv.w*v3.z;
            float aw = wv.x*v0.w + wv.y*v1.w + wv.z*v2.w + wv.w*v3.w;
            float* dst = stg + p*33 + c*4;   // stride 33: store banks p+4c+e, conflict-free
            dst[0] = ax; dst[1] = ay; dst[2] = az; dst[3] = aw;
        }
        __syncthreads();
        // consume: 32 channels; each thread serves its 2 points, uniform weight LDS.128
        #pragma unroll 1
        for (int c2 = 0; c2 < 32; c2++) {
            float fA = stg[tid*33 + c2];            // banks tid+c2: conflict-free
            float fB = stg[(tid + BD)*33 + c2];
            u64 dA = pk2(fA, fA), dB = pk2(fB, fB);
            const ulonglong2* wr = (const ulonglong2*)(s + OFF_W1 + (q*32 + c2)*64);
            #pragma unroll
            for (int t = 0; t < 16; t++) {
                ulonglong2 w = wr[t];
                fma2(accA[2*t], dA, w.x); fma2(accA[2*t+1], dA, w.y);
                fma2(accB[2*t], dB, w.x); fma2(accB[2*t+1], dB, w.y);
            }
        }
        __syncthreads();
    }

    // ---- Fourier features (rows 128..191 sin, 192..255 cos) ----
    #pragma unroll 1
    for (int m = 0; m < 64; m++) {
        float4 bg = *(const float4*)(s + OFF_BG4 + m*4);
        float sA, cA, sB, cB;
        sincosf(6.28318530717958647692f * (pxA*bg.x + pyA*bg.y + pzA*bg.z), &sA, &cA);
        sincosf(6.28318530717958647692f * (pxB*bg.x + pyB*bg.y + pzB*bg.z), &sB, &cB);
        u64 dsA = pk2(sA, sA), dcA = pk2(cA, cA);
        u64 dsB = pk2(sB, sB), dcB = pk2(cB, cB);
        const ulonglong2* wrs = (const ulonglong2*)(s + OFF_W1 + (128 + m)*64);
        const ulonglong2* wrc = (const ulonglong2*)(s + OFF_W1 + (192 + m)*64);
        #pragma unroll
        for (int t = 0; t < 16; t++) {
            ulonglong2 w = wrs[t];
            fma2(accA[2*t], dsA, w.x); fma2(accA[2*t+1], dsA, w.y);
            fma2(accB[2*t], dsB, w.x); fma2(accB[2*t+1], dsB, w.y);
        }
        #pragma unroll
        for (int t = 0; t < 16; t++) {
            ulonglong2 w = wrc[t];
            fma2(accA[2*t], dcA, w.x); fma2(accA[2*t+1], dcA, w.y);
            fma2(accB[2*t], dcB, w.x); fma2(accB[2*t+1], dcB, w.y);
        }
    }

    // ---- tails: staging buffer is free for all threads after the q-loop barrier;
    //      each thread touches only its own column, so no further syncs needed ----
    #pragma unroll
    for (int t = 0; t < 32; t++) {
        float lo, hi; upk2(relu2(accA[t]), lo, hi);
        stg[(2*t)*BD + tid] = lo; stg[(2*t+1)*BD + tid] = hi;
        accB[t] = relu2(accB[t]);
    }
    float outA = mlp_tail(s, stg, tid);

    #pragma unroll
    for (int t = 0; t < 32; t++) {
        float lo, hi; upk2(accB[t], lo, hi);
        stg[(2*t)*BD + tid] = lo; stg[(2*t+1)*BD + tid] = hi;
    }
    float outB = mlp_tail(s, stg, tid);

    out[pA] = outA;
    out[pB] = outB;
}

extern "C" void kernel_launch(void* const* d_in, const int* in_sizes, int n_in,
                              void* d_out, int out_size) {
    const float* features = (const float*)d_in[0];
    const float* points   = (const float*)d_in[1];
    const float* kmat     = (const float*)d_in[2];
    const float* rt       = (const float*)d_in[3];
    const float* Bg       = (const float*)d_in[4];
    const float* W1       = (const float*)d_in[5];
    const float* b1       = (const float*)d_in[6];
    const float* W2       = (const float*)d_in[7];
    const float* b2       = (const float*)d_in[8];
    const float* W3       = (const float*)d_in[9];
    const float* b3       = (const float*)d_in[10];
    const float* W4       = (const float*)d_in[11];
    const float* b4       = (const float*)d_in[12];
    float* out = (float*)d_out;

    transpose_kernel<<<FEATTOT/256, 256>>>(features);

    cudaFuncSetAttribute(decoder_kernel,
                         cudaFuncAttributeMaxDynamicSharedMemorySize, SMEM_BYTES);
    decoder_kernel<<<TOTPTS/PPB, BD, SMEM_BYTES>>>(
        points, kmat, rt, Bg, W1, b1, W2, b2, W3, b3, W4, b4, out);
}